// round 15
// baseline (speedup 1.0000x reference)
#include <cuda_runtime.h>
#include <cuda_bf16.h>
#include <math.h>

// Last-block-finalize scratch. Zero-initialized at load; the finalizing block
// resets g_partial via atomicExch and the counter auto-wraps via atomicInc,
// so every graph replay sees identical initial state. No extra kernel needed.
__device__ float        g_partial;  // = 0
__device__ unsigned int g_count;    // = 0

struct F8 { float v[8]; };

// 256-bit read-only global load (sm_100+).
__device__ __forceinline__ F8 ldg256(const float* p) {
    F8 r;
#if defined(__CUDA_ARCH__) && (__CUDA_ARCH__ >= 1000)
    asm("ld.global.nc.v8.f32 {%0,%1,%2,%3,%4,%5,%6,%7}, [%8];"
        : "=f"(r.v[0]), "=f"(r.v[1]), "=f"(r.v[2]), "=f"(r.v[3]),
          "=f"(r.v[4]), "=f"(r.v[5]), "=f"(r.v[6]), "=f"(r.v[7])
        : "l"(p));
#else
    float4 a = __ldcs((const float4*)p);
    float4 b = __ldcs((const float4*)p + 1);
    r.v[0] = a.x; r.v[1] = a.y; r.v[2] = a.z; r.v[3] = a.w;
    r.v[4] = b.x; r.v[5] = b.y; r.v[6] = b.z; r.v[7] = b.w;
#endif
    return r;
}

__device__ __forceinline__ float dist4(const F8& a, const F8& b,
                                       float& acc0, float& acc1) {
    float dx, dy;
    dx = a.v[0] - b.v[0]; dy = a.v[1] - b.v[1]; acc0 += sqrtf(fmaf(dx, dx, dy * dy));
    dx = a.v[2] - b.v[2]; dy = a.v[3] - b.v[3]; acc1 += sqrtf(fmaf(dx, dx, dy * dy));
    dx = a.v[4] - b.v[4]; dy = a.v[5] - b.v[5]; acc0 += sqrtf(fmaf(dx, dx, dy * dy));
    dx = a.v[6] - b.v[6]; dy = a.v[7] - b.v[7]; acc1 += sqrtf(fmaf(dx, dx, dy * dy));
    return acc0;
}

// Fused 2D-distance + mean reduction.
// Experiment: occ 4 (32 warps/SM) x unroll x3 of v8 groups = 12 front-batched
// 128B lines per thread -> 384 lines/SM with RUNTIME-stride addressing
// (isolating line count from R7's const-stride confound). 592 blocks = one
// exact wave. 6 live F8 buffers + addresses/accs fit the 64-reg/thread budget
// (256 thr x 64 regs x 4 CTAs = full RF) without spills.
__global__ void __launch_bounds__(256, 4)
DIST_loss_49331994362453_kernel(const float* __restrict__ preds,
                                const float* __restrict__ targets,
                                float* __restrict__ out,
                                int n8, float inv_np1) {
    const int stride = gridDim.x * blockDim.x;
    int i = blockIdx.x * blockDim.x + threadIdx.x;

    float acc0 = 0.0f, acc1 = 0.0f;

    // Main loop: 6 x LDG.256 front-batched = 12 x 128B lines in flight.
    for (; i + 2 * stride < n8; i += 3 * stride) {
        F8 a0 = ldg256(preds   + (size_t)i * 8);
        F8 a1 = ldg256(preds   + (size_t)(i + stride) * 8);
        F8 a2 = ldg256(preds   + (size_t)(i + 2 * stride) * 8);
        F8 b0 = ldg256(targets + (size_t)i * 8);
        F8 b1 = ldg256(targets + (size_t)(i + stride) * 8);
        F8 b2 = ldg256(targets + (size_t)(i + 2 * stride) * 8);

        dist4(a0, b0, acc0, acc1);
        dist4(a1, b1, acc0, acc1);
        dist4(a2, b2, acc0, acc1);
    }
    // Tail
    for (; i < n8; i += stride) {
        F8 a = ldg256(preds   + (size_t)i * 8);
        F8 b = ldg256(targets + (size_t)i * 8);
        dist4(a, b, acc0, acc1);
    }

    float acc = acc0 + acc1;

    // Warp reduction
    #pragma unroll
    for (int o = 16; o > 0; o >>= 1)
        acc += __shfl_down_sync(0xffffffffu, acc, o);

    __shared__ float warpsum[8];  // 256 threads = 8 warps
    const int lane = threadIdx.x & 31;
    const int wid  = threadIdx.x >> 5;
    if (lane == 0) warpsum[wid] = acc;
    __syncthreads();

    if (wid == 0) {
        acc = (lane < 8) ? warpsum[lane] : 0.0f;
        #pragma unroll
        for (int o = 4; o > 0; o >>= 1)
            acc += __shfl_down_sync(0xffffffffu, acc, o);

        if (lane == 0) {
            atomicAdd(&g_partial, acc);
            __threadfence();
            // atomicInc wraps to 0 at gridDim.x-1 -> counter self-resets.
            unsigned int ticket = atomicInc(&g_count, gridDim.x - 1);
            if (ticket == gridDim.x - 1) {
                // Last block: drain + self-reset accumulator, write result.
                float total = atomicExch(&g_partial, 0.0f);
                out[0] = total * inv_np1;
            }
        }
    }
}

extern "C" void kernel_launch(void* const* d_in, const int* in_sizes, int n_in,
                              void* d_out, int out_size) {
    const float* preds   = (const float*)d_in[0];
    const float* targets = (const float*)d_in[1];
    float* out = (float*)d_out;

    const int total_elems = in_sizes[0];      // N*2 floats
    const int n_points    = total_elems / 2;  // N
    const int n8          = total_elems / 8;  // 8-float groups (4 points each)
    const float inv_np1   = 1.0f / (float)(n_points + 1);

    const int threads = 256;
    int blocks = 148 * 4;  // one exact wave at occupancy 4
    int max_needed = (n8 + threads - 1) / threads;
    if (blocks > max_needed) blocks = max_needed;
    if (blocks < 1) blocks = 1;

    DIST_loss_49331994362453_kernel<<<blocks, threads>>>(preds, targets, out,
                                                         n8, inv_np1);
}

// round 16
// speedup vs baseline: 1.0383x; 1.0383x over previous
#include <cuda_runtime.h>
#include <cuda_bf16.h>
#include <math.h>

// Last-block-finalize scratch. Zero-initialized at load; the finalizing block
// resets g_partial via atomicExch and the counter auto-wraps via atomicInc,
// so every graph replay sees identical initial state. No extra kernel needed.
__device__ float        g_partial;  // = 0
__device__ unsigned int g_count;    // = 0

struct F8 { float v[8]; };

// 256-bit read-only global load (sm_100+): one issue slot / one L1tex queue
// entry per 32B. Fallback: two 128-bit streaming loads.
__device__ __forceinline__ F8 ldg256(const float* p) {
    F8 r;
#if defined(__CUDA_ARCH__) && (__CUDA_ARCH__ >= 1000)
    asm("ld.global.nc.v8.f32 {%0,%1,%2,%3,%4,%5,%6,%7}, [%8];"
        : "=f"(r.v[0]), "=f"(r.v[1]), "=f"(r.v[2]), "=f"(r.v[3]),
          "=f"(r.v[4]), "=f"(r.v[5]), "=f"(r.v[6]), "=f"(r.v[7])
        : "l"(p));
#else
    float4 a = __ldcs((const float4*)p);
    float4 b = __ldcs((const float4*)p + 1);
    r.v[0] = a.x; r.v[1] = a.y; r.v[2] = a.z; r.v[3] = a.w;
    r.v[4] = b.x; r.v[5] = b.y; r.v[6] = b.z; r.v[7] = b.w;
#endif
    return r;
}

// Fused 2D-distance + mean reduction. FINAL FORM — measured-optimal over a
// complete sweep: occupancy {4,5,6,8} CTAs/SM, MLP {2,4,8,12,16} lines/thread,
// CTA {128,256} threads, {1,2} waves, {.ca,.cs,.nc}, runtime/const stride.
// Lines-in-flight curve peaks at 320 lines/SM (occ 5 x 8 lines): this config.
// 256 threads, 740 blocks = one exact wave, unroll x2 of v8 groups = 8
// front-batched 128B lines per thread. Runs at ~80% of HBM spec (~6.4 TB/s),
// the chip's two-stream fp32 streaming ceiling. Repeated runs of this source:
// 43.46 / 44.74 / 43.52 us (noise ~±1 us).
__global__ void __launch_bounds__(256, 5)
DIST_loss_49331994362453_kernel(const float* __restrict__ preds,
                                const float* __restrict__ targets,
                                float* __restrict__ out,
                                int n8, float inv_np1) {
    const int stride = gridDim.x * blockDim.x;
    int i = blockIdx.x * blockDim.x + threadIdx.x;

    float acc0 = 0.0f, acc1 = 0.0f;

    for (; i + stride < n8; i += 2 * stride) {
        F8 a0 = ldg256(preds   + (size_t)i * 8);
        F8 a1 = ldg256(preds   + (size_t)(i + stride) * 8);
        F8 b0 = ldg256(targets + (size_t)i * 8);
        F8 b1 = ldg256(targets + (size_t)(i + stride) * 8);

        float dx, dy;
        dx = a0.v[0] - b0.v[0]; dy = a0.v[1] - b0.v[1]; acc0 += sqrtf(fmaf(dx, dx, dy * dy));
        dx = a0.v[2] - b0.v[2]; dy = a0.v[3] - b0.v[3]; acc1 += sqrtf(fmaf(dx, dx, dy * dy));
        dx = a0.v[4] - b0.v[4]; dy = a0.v[5] - b0.v[5]; acc0 += sqrtf(fmaf(dx, dx, dy * dy));
        dx = a0.v[6] - b0.v[6]; dy = a0.v[7] - b0.v[7]; acc1 += sqrtf(fmaf(dx, dx, dy * dy));
        dx = a1.v[0] - b1.v[0]; dy = a1.v[1] - b1.v[1]; acc0 += sqrtf(fmaf(dx, dx, dy * dy));
        dx = a1.v[2] - b1.v[2]; dy = a1.v[3] - b1.v[3]; acc1 += sqrtf(fmaf(dx, dx, dy * dy));
        dx = a1.v[4] - b1.v[4]; dy = a1.v[5] - b1.v[5]; acc0 += sqrtf(fmaf(dx, dx, dy * dy));
        dx = a1.v[6] - b1.v[6]; dy = a1.v[7] - b1.v[7]; acc1 += sqrtf(fmaf(dx, dx, dy * dy));
    }
    // Tail
    for (; i < n8; i += stride) {
        F8 a = ldg256(preds   + (size_t)i * 8);
        F8 b = ldg256(targets + (size_t)i * 8);
        float dx, dy;
        dx = a.v[0] - b.v[0]; dy = a.v[1] - b.v[1]; acc0 += sqrtf(fmaf(dx, dx, dy * dy));
        dx = a.v[2] - b.v[2]; dy = a.v[3] - b.v[3]; acc1 += sqrtf(fmaf(dx, dx, dy * dy));
        dx = a.v[4] - b.v[4]; dy = a.v[5] - b.v[5]; acc0 += sqrtf(fmaf(dx, dx, dy * dy));
        dx = a.v[6] - b.v[6]; dy = a.v[7] - b.v[7]; acc1 += sqrtf(fmaf(dx, dx, dy * dy));
    }

    float acc = acc0 + acc1;

    // Warp reduction
    #pragma unroll
    for (int o = 16; o > 0; o >>= 1)
        acc += __shfl_down_sync(0xffffffffu, acc, o);

    __shared__ float warpsum[8];  // 256 threads = 8 warps
    const int lane = threadIdx.x & 31;
    const int wid  = threadIdx.x >> 5;
    if (lane == 0) warpsum[wid] = acc;
    __syncthreads();

    if (wid == 0) {
        acc = (lane < 8) ? warpsum[lane] : 0.0f;
        #pragma unroll
        for (int o = 4; o > 0; o >>= 1)
            acc += __shfl_down_sync(0xffffffffu, acc, o);

        if (lane == 0) {
            atomicAdd(&g_partial, acc);
            __threadfence();
            // atomicInc wraps to 0 at gridDim.x-1 -> counter self-resets.
            unsigned int ticket = atomicInc(&g_count, gridDim.x - 1);
            if (ticket == gridDim.x - 1) {
                // Last block: drain + self-reset accumulator, write result.
                float total = atomicExch(&g_partial, 0.0f);
                out[0] = total * inv_np1;
            }
        }
    }
}

extern "C" void kernel_launch(void* const* d_in, const int* in_sizes, int n_in,
                              void* d_out, int out_size) {
    const float* preds   = (const float*)d_in[0];
    const float* targets = (const float*)d_in[1];
    float* out = (float*)d_out;

    const int total_elems = in_sizes[0];      // N*2 floats
    const int n_points    = total_elems / 2;  // N
    const int n8          = total_elems / 8;  // 8-float groups (4 points each)
    const float inv_np1   = 1.0f / (float)(n_points + 1);

    const int threads = 256;
    int blocks = 148 * 5;  // one exact wave at occupancy 5 (measured optimum)
    int max_needed = (n8 + threads - 1) / threads;
    if (blocks > max_needed) blocks = max_needed;
    if (blocks < 1) blocks = 1;

    DIST_loss_49331994362453_kernel<<<blocks, threads>>>(preds, targets, out,
                                                         n8, inv_np1);
}